// round 13
// baseline (speedup 1.0000x reference)
#include <cuda_runtime.h>
#include <cuda_bf16.h>
#include <cstdint>
#include <math.h>

// ---------------- problem constants ----------------
constexpr int Bdim = 4;
constexpr int Tdim = 96;
constexpr int Ndim = 512;
constexpr int Hdim = 128;

// ---------------- helpers ----------------
__device__ __forceinline__ uint32_t smem_u32(const void* p) {
    uint32_t a;
    asm("{ .reg .u64 t; cvta.to.shared.u64 t, %1; cvt.u32.u64 %0, t; }"
        : "=r"(a) : "l"(p));
    return a;
}

#define LDSM4(r, addr)                                                        \
    asm volatile("ldmatrix.sync.aligned.m8n8.x4.shared.b16 {%0,%1,%2,%3}, [%4];" \
                 : "=r"((r)[0]), "=r"((r)[1]), "=r"((r)[2]), "=r"((r)[3])     \
                 : "r"(addr))

#define MMA16816(d, a, b0, b1)                                                \
    asm volatile("mma.sync.aligned.m16n8k16.row.col.f32.bf16.bf16.f32 "       \
                 "{%0,%1,%2,%3}, {%4,%5,%6,%7}, {%8,%9}, {%0,%1,%2,%3};"      \
                 : "+f"((d)[0]), "+f"((d)[1]), "+f"((d)[2]), "+f"((d)[3])     \
                 : "r"((a)[0]), "r"((a)[1]), "r"((a)[2]), "r"((a)[3]),        \
                   "r"(b0), "r"(b1))

constexpr int LDS_STRIDE = 136;  // 128 + 8 bf16 pad -> conflict-free smem

// fp32 x4 -> hi/lo bf16 pairs
__device__ __forceinline__ void split4(float4 v, uint2& hp, uint2& lp) {
    __nv_bfloat162 h0 = __float22bfloat162_rn(make_float2(v.x, v.y));
    __nv_bfloat162 h1 = __float22bfloat162_rn(make_float2(v.z, v.w));
    float2 h0f = __bfloat1622float2(h0);
    float2 h1f = __bfloat1622float2(h1);
    __nv_bfloat162 l0 = __float22bfloat162_rn(make_float2(v.x - h0f.x, v.y - h0f.y));
    __nv_bfloat162 l1 = __float22bfloat162_rn(make_float2(v.z - h1f.x, v.w - h1f.y));
    hp.x = *reinterpret_cast<uint32_t*>(&h0);
    hp.y = *reinterpret_cast<uint32_t*>(&h1);
    lp.x = *reinterpret_cast<uint32_t*>(&l0);
    lp.y = *reinterpret_cast<uint32_t*>(&l1);
}

// ---------------- single fused kernel: GEMM1 + EMA + gate + GEMM2 ----------------
// Grid: 128 CTAs = (b 0..3) x (16-row n-chunk, 32). Block: 256 (8 warps).
// Per t: stage x tile -> GEMM1 (primary 3-pass, gating 1-pass) -> register EMA
// scan + sigmoid -> gated staged to smem (bf16 hi/lo) -> GEMM2 (3-pass, W_con
// resident) -> direct store of out rows. No intermediate global traffic.
// smem: WeHi 256r | WeLo 128r (primary) | WcHi 128r | WcLo 128r | A hi/lo 16r | G hi/lo 16r
__global__ __launch_bounds__(256, 1)
void mamba_one(const float* __restrict__ x,
               const float* __restrict__ W_exp, const float* __restrict__ b_exp,
               const float* __restrict__ W_con, const float* __restrict__ b_con,
               float* __restrict__ out) {
    extern __shared__ char smem[];
    __nv_bfloat16* sWeHi = reinterpret_cast<__nv_bfloat16*>(smem);   // 256 rows
    __nv_bfloat16* sWeLo = sWeHi + 256 * LDS_STRIDE;                 // 128 rows
    __nv_bfloat16* sWcHi = sWeLo + 128 * LDS_STRIDE;                 // 128 rows
    __nv_bfloat16* sWcLo = sWcHi + 128 * LDS_STRIDE;                 // 128 rows
    __nv_bfloat16* sAhi  = sWcLo + 128 * LDS_STRIDE;                 // 16 rows
    __nv_bfloat16* sAlo  = sAhi + 16 * LDS_STRIDE;
    __nv_bfloat16* sGhi  = sAlo + 16 * LDS_STRIDE;                   // 16 rows
    __nv_bfloat16* sGlo  = sGhi + 16 * LDS_STRIDE;

    const int tid  = threadIdx.x;
    const int wid  = tid >> 5;
    const int lane = tid & 31;
    const int b    = blockIdx.x >> 5;
    const int n0   = (blockIdx.x & 31) * 16;

    // inline weight conversion (L2-served after first CTAs)
#pragma unroll 4
    for (int it = 0; it < 32; ++it) {           // W_exp: 8192 float4
        int i = tid + it * 256;
        int r = i >> 5, c4 = (i & 31) << 2;
        float4 v = *reinterpret_cast<const float4*>(W_exp + (size_t)r * 128 + c4);
        uint2 hp, lp;
        split4(v, hp, lp);
        int off = r * LDS_STRIDE + c4;
        *reinterpret_cast<uint2*>(sWeHi + off) = hp;
        if (r < 128) *reinterpret_cast<uint2*>(sWeLo + off) = lp;  // primary lo only
    }
#pragma unroll 4
    for (int it = 0; it < 16; ++it) {           // W_con: 4096 float4
        int i = tid + it * 256;
        int r = i >> 5, c4 = (i & 31) << 2;
        float4 v = *reinterpret_cast<const float4*>(W_con + (size_t)r * 128 + c4);
        uint2 hp, lp;
        split4(v, hp, lp);
        int off = r * LDS_STRIDE + c4;
        *reinterpret_cast<uint2*>(sWcHi + off) = hp;
        *reinterpret_cast<uint2*>(sWcLo + off) = lp;
    }

    // ldmatrix addresses
    uint32_t aHiAd, aLoAd, b1HiAd[2], b1LoAd;        // GEMM1
    uint32_t a2HiAd, a2LoAd, b2HiAd, b2LoAd;         // GEMM2
    {
        const uint32_t aoff = ((lane & 15) * LDS_STRIDE + (lane >> 4) * 8) * 2;
        aHiAd  = smem_u32(sAhi) + aoff;
        aLoAd  = smem_u32(sAlo) + aoff;
        a2HiAd = smem_u32(sGhi) + aoff;
        a2LoAd = smem_u32(sGlo) + aoff;
        int bc = ((lane >> 3) & 1) * 8;
        int brBase = 16 * wid + ((lane >> 4) << 3) + (lane & 7);
        b1HiAd[0] = smem_u32(sWeHi) + (brBase * LDS_STRIDE + bc) * 2;           // primary hi
        b1HiAd[1] = smem_u32(sWeHi) + ((128 + brBase) * LDS_STRIDE + bc) * 2;   // gating hi
        b1LoAd    = smem_u32(sWeLo) + (brBase * LDS_STRIDE + bc) * 2;           // primary lo
        b2HiAd    = smem_u32(sWcHi) + (brBase * LDS_STRIDE + bc) * 2;
        b2LoAd    = smem_u32(sWcLo) + (brBase * LDS_STRIDE + bc) * 2;
    }

    const int gr = lane >> 2;
    const int gc = (lane & 3) * 2;
    float bp[2][2], bg[2][2], bo[2][2];
#pragma unroll
    for (int jj = 0; jj < 2; ++jj) {
        bp[jj][0] = b_exp[16 * wid + jj * 8 + gc];
        bp[jj][1] = b_exp[16 * wid + jj * 8 + gc + 1];
        bg[jj][0] = b_exp[128 + 16 * wid + jj * 8 + gc];
        bg[jj][1] = b_exp[128 + 16 * wid + jj * 8 + gc + 1];
        bo[jj][0] = b_con[16 * wid + jj * 8 + gc];
        bo[jj][1] = b_con[16 * wid + jj * 8 + gc + 1];
    }

    // EMA state (per-lane share of this warp's 16x16 gating block)
    float s[2][4];
#pragma unroll
    for (int jj = 0; jj < 2; ++jj)
#pragma unroll
        for (int q = 0; q < 4; ++q) s[jj][q] = 0.0f;

    // prefetch t = 0: 16x128 fp32 = 512 float4, 2 per thread
    float4 pf[2];
    {
        size_t rb = ((size_t)(b * Tdim) * Ndim + n0) * 128;
#pragma unroll
        for (int it = 0; it < 2; ++it) {
            int i = tid + it * 256;
            int r = i >> 5, c4 = (i & 31) << 2;
            pf[it] = *reinterpret_cast<const float4*>(x + rb + (size_t)r * 128 + c4);
        }
    }

    for (int t = 0; t < Tdim; ++t) {
        // stage A tile: fp32 -> split bf16 planes
        // (this top barrier also guarantees all warps finished last iter's
        //  GEMM2 reads of sG before it is rewritten below)
#pragma unroll
        for (int it = 0; it < 2; ++it) {
            int i = tid + it * 256;
            int r = i >> 5, c4 = (i & 31) << 2;
            uint2 hp, lp;
            split4(pf[it], hp, lp);
            int off = r * LDS_STRIDE + c4;
            *reinterpret_cast<uint2*>(sAhi + off) = hp;
            *reinterpret_cast<uint2*>(sAlo + off) = lp;
        }
        __syncthreads();

        // prefetch next t (hidden under MMAs)
        if (t + 1 < Tdim) {
            size_t rb = ((size_t)(b * Tdim + t + 1) * Ndim + n0) * 128;
#pragma unroll
            for (int it = 0; it < 2; ++it) {
                int i = tid + it * 256;
                int r = i >> 5, c4 = (i & 31) << 2;
                pf[it] = *reinterpret_cast<const float4*>(x + rb + (size_t)r * 128 + c4);
            }
        }

        // ---- GEMM1 ----
        float acc[2][2][4];   // [blk: 0=primary 1=gating][jj][q]
#pragma unroll
        for (int p = 0; p < 2; ++p)
#pragma unroll
            for (int jj = 0; jj < 2; ++jj)
#pragma unroll
                for (int q = 0; q < 4; ++q) acc[p][jj][q] = 0.0f;

#pragma unroll
        for (int kk = 0; kk < 8; ++kk) {
            const uint32_t ko = kk * 32;
            uint32_t ah[4], al[4], bh[2][4], bl[4];
            LDSM4(ah, aHiAd + ko);
            LDSM4(bh[0], b1HiAd[0] + ko);
            LDSM4(bh[1], b1HiAd[1] + ko);
            LDSM4(al, aLoAd + ko);
            LDSM4(bl, b1LoAd + ko);
#pragma unroll
            for (int jj = 0; jj < 2; ++jj) {     // primary: 3-pass
                const int wh = jj * 2;
                float* d = acc[0][jj];
                MMA16816(d, ah, bh[0][wh], bh[0][wh + 1]);
                MMA16816(d, ah, bl[wh],    bl[wh + 1]);
                MMA16816(d, al, bh[0][wh], bh[0][wh + 1]);
            }
#pragma unroll
            for (int jj = 0; jj < 2; ++jj) {     // gating: 1-pass
                const int wh = jj * 2;
                MMA16816(acc[1][jj], ah, bh[1][wh], bh[1][wh + 1]);
            }
        }

        // ---- scan + gate + split into sG ----
#pragma unroll
        for (int jj = 0; jj < 2; ++jj) {
            float gt[4];
#pragma unroll
            for (int q = 0; q < 4; ++q) {
                float gv = acc[1][jj][q] + bg[jj][q & 1];
                s[jj][q] = fmaf(0.9f, s[jj][q], 0.1f * gv);
                float sig = 1.0f / (1.0f + __expf(-s[jj][q]));
                gt[q] = (acc[0][jj][q] + bp[jj][q & 1]) * sig;
            }
            const int col = 16 * wid + jj * 8 + gc;
#pragma unroll
            for (int h2 = 0; h2 < 2; ++h2) {
                float2 pr2 = make_float2(gt[h2 * 2], gt[h2 * 2 + 1]);
                __nv_bfloat162 hi2 = __float22bfloat162_rn(pr2);
                float2 hif = __bfloat1622float2(hi2);
                __nv_bfloat162 lo2 = __float22bfloat162_rn(
                    make_float2(pr2.x - hif.x, pr2.y - hif.y));
                int row = gr + h2 * 8;
                *reinterpret_cast<uint32_t*>(sGhi + row * LDS_STRIDE + col) =
                    *reinterpret_cast<uint32_t*>(&hi2);
                *reinterpret_cast<uint32_t*>(sGlo + row * LDS_STRIDE + col) =
                    *reinterpret_cast<uint32_t*>(&lo2);
            }
        }
        __syncthreads();   // sG complete, visible to all warps

        // ---- GEMM2: out rows = gated(16x128) * W_con^T + b_con ----
        float acc2[2][4];
#pragma unroll
        for (int jj = 0; jj < 2; ++jj)
#pragma unroll
            for (int q = 0; q < 4; ++q) acc2[jj][q] = 0.0f;

#pragma unroll
        for (int kk = 0; kk < 8; ++kk) {
            const uint32_t ko = kk * 32;
            uint32_t a2h[4], a2l[4], b2h[4], b2l[4];
            LDSM4(a2h, a2HiAd + ko);
            LDSM4(b2h, b2HiAd + ko);
            LDSM4(a2l, a2LoAd + ko);
            LDSM4(b2l, b2LoAd + ko);
#pragma unroll
            for (int jj = 0; jj < 2; ++jj) {
                const int wh = jj * 2;
                float* d = acc2[jj];
                MMA16816(d, a2h, b2h[wh], b2h[wh + 1]);
                MMA16816(d, a2h, b2l[wh], b2l[wh + 1]);
                MMA16816(d, a2l, b2h[wh], b2h[wh + 1]);
            }
        }

        // direct store of out rows
        {
            size_t rowBase = (size_t)(b * Tdim + t) * Ndim + n0;
#pragma unroll
            for (int jj = 0; jj < 2; ++jj) {
                const int col = 16 * wid + jj * 8 + gc;
                float2 o0, o1;
                o0.x = acc2[jj][0] + bo[jj][0]; o0.y = acc2[jj][1] + bo[jj][1];
                o1.x = acc2[jj][2] + bo[jj][0]; o1.y = acc2[jj][3] + bo[jj][1];
                *reinterpret_cast<float2*>(&out[(rowBase + gr) * 128 + col])     = o0;
                *reinterpret_cast<float2*>(&out[(rowBase + gr + 8) * 128 + col]) = o1;
            }
        }
    }
}

// ---------------- launch ----------------
extern "C" void kernel_launch(void* const* d_in, const int* in_sizes, int n_in,
                              void* d_out, int out_size) {
    const float* x     = (const float*)d_in[0];
    const float* W_exp = (const float*)d_in[1];
    const float* b_exp = (const float*)d_in[2];
    const float* W_con = (const float*)d_in[3];
    const float* b_con = (const float*)d_in[4];
    float* out = (float*)d_out;

    // smem: (256 + 128 + 128 + 128 + 4*16) rows * 136 * 2B = 191,488 bytes
    constexpr int SMEM = (256 + 128 + 128 + 128 + 64) * LDS_STRIDE * 2;
    cudaFuncSetAttribute(mamba_one, cudaFuncAttributeMaxDynamicSharedMemorySize, SMEM);

    mamba_one<<<Bdim * 32, 256, SMEM>>>(x, W_exp, b_exp, W_con, b_con, out);
}